// round 8
// baseline (speedup 1.0000x reference)
#include <cuda_runtime.h>
#include <cuda_fp16.h>
#include <math.h>
#include <stdint.h>

#define NCB   8
#define MEMB  1024
#define DEMB  128
#define HLAT  64
#define BATCH 256
#define LPER  (BATCH*HLAT)              /* 16384 per codebook */
#define ZQ_ELEMS (BATCH*NCB*DEMB*HLAT)  /* 16777216 */
#define IDX_ELEMS (BATCH*NCB*HLAT)      /* 131072 */

// ---------------- device scratch ----------------
__device__ int   g_indices[NCB*LPER];
__device__ float g_esq[NCB*MEMB];
__device__ int   g_esqmaxb[NCB];          // max esq per codebook (float bits, >0)
__device__ float g_xsq[NCB*LPER];
__device__ float g_part[2048];
__device__ float g_ent[NCB];
__device__ int   g_ucount;
__device__ int   g_ulist[NCB*LPER];
__device__ unsigned long long g_fixkey[NCB*LPER];
// pre-swizzled fp16 embedding tiles (e*256): [n][mchunk 8][row 128][k 128]
__device__ __half g_bh[NCB*MEMB*DEMB];

// ---------------- PTX helpers ----------------
__device__ __forceinline__ uint32_t smem_u32(const void* p) {
    uint32_t a;
    asm("{ .reg .u64 t; cvta.to.shared.u64 t, %1; cvt.u32.u64 %0, t; }" : "=r"(a) : "l"(p));
    return a;
}
__device__ __forceinline__ void ldsm4(uint32_t* r, uint32_t addr) {
    asm volatile("ldmatrix.sync.aligned.m8n8.x4.shared.b16 {%0,%1,%2,%3}, [%4];"
        : "=r"(r[0]), "=r"(r[1]), "=r"(r[2]), "=r"(r[3]) : "r"(addr));
}
__device__ __forceinline__ void mma_f16(float* c, const uint32_t* a, const uint32_t* b) {
    asm volatile("mma.sync.aligned.m16n8k16.row.col.f32.f16.f16.f32 "
        "{%0,%1,%2,%3}, {%4,%5,%6,%7}, {%8,%9}, {%0,%1,%2,%3};"
        : "+f"(c[0]), "+f"(c[1]), "+f"(c[2]), "+f"(c[3])
        : "r"(a[0]), "r"(a[1]), "r"(a[2]), "r"(a[3]), "r"(b[0]), "r"(b[1]));
}
__device__ __forceinline__ void cp16(uint32_t dst, const void* src) {
    asm volatile("cp.async.cg.shared.global [%0], [%1], 16;" :: "r"(dst), "l"(src) : "memory");
}
#define CP_COMMIT() asm volatile("cp.async.commit_group;" ::: "memory")
#define CP_WAIT(n)  asm volatile("cp.async.wait_group %0;" :: "n"(n) : "memory")

// ---------------- e_sq (exact sequential) + per-n max + ucount reset ----------------
__global__ void esq_kernel(const float* __restrict__ emb) {
    int t = blockIdx.x * blockDim.x + threadIdx.x;
    if (t == 0) g_ucount = 0;
    if (t >= NCB*MEMB) return;
    const float* row = emb + (size_t)t * DEMB;
    float acc = 0.f;
    #pragma unroll 8
    for (int d = 0; d < DEMB; d++) {
        float v = row[d];
        acc = __fadd_rn(acc, __fmul_rn(v, v));
    }
    g_esq[t] = acc;
    atomicMax(&g_esqmaxb[t >> 10], __float_as_int(acc));   // acc > 0
}

// ---------------- x_sq (exact sequential) ----------------
__global__ void __launch_bounds__(256)
xsq_kernel(const float* __restrict__ x) {
    __shared__ float tile[8192];
    const int n = blockIdx.x & 7, b = blockIdx.x >> 3, tid = threadIdx.x;
    const size_t base = (size_t)b*65536 + (size_t)n*8192;
    for (int i = tid; i < 8192; i += 256) tile[i] = x[base + i];
    __syncthreads();
    if (tid < 64) {
        float acc = 0.f;
        #pragma unroll 8
        for (int d = 0; d < DEMB; d++) {
            float v = tile[d*64 + tid];
            acc = __fadd_rn(acc, __fmul_rn(v, v));
        }
        g_xsq[n*LPER + b*HLAT + tid] = acc;
    }
}

// ---------------- embedding -> swizzled fp16 (e*256) tiles ----------------
__global__ void bprep_kernel(const float* __restrict__ emb) {
    int u = blockIdx.x * blockDim.x + threadIdx.x;
    if (u >= NCB*MEMB*DEMB) return;
    float v = emb[u] * 256.0f;               // exact scale
    int d = u & 127, m = (u >> 7) & 1023, n = u >> 17;
    int row = m & 127, mc = m >> 7;
    int elem = ((n*8 + mc)*128 + row)*128 + (((d >> 3) ^ (row & 7)) << 3) + (d & 7);
    g_bh[elem] = __float2half_rn(v);
}

// ---------------- pass 1: fp16 2-MMA approximate argmin ----------------
// CTA = (n, batch row). 256 threads = 8 warps = 2(l) x 4(m); warp tile 32x32.
// m-chunks of 128 codes (8 iters), B double-buffered via cp.async.
// acc = (Xhi + Xlo) . (256*E)_f16 ; dist_proxy = esq - acc/128.
__global__ void __launch_bounds__(256, 2)
argmin_mma(const float* __restrict__ x) {
    extern __shared__ char smraw[];
    uint32_t sraw = smem_u32(smraw);
    uint32_t sb = (sraw + 1023u) & ~1023u;
    char* sm = smraw + (sb - sraw);
    __half* Ahi = (__half*)(sm);              // 16KB @0
    __half* Alo = (__half*)(sm + 16384);      // 16KB
    // B buffers: buf0 @32768 (32KB), buf1 @65536 (32KB)
    float* esq_s = (float*)(sm + 98304);      // 4KB
    float* sbest = (float*)(sm + 102400);     // 256 f32
    float* ssec  = (float*)(sm + 103424);     // 256 f32
    int*   sidx  = (int*)  (sm + 104448);     // 256 int

    const int n  = blockIdx.x >> 8;
    const int lt = blockIdx.x & 255;          // batch row b
    const int l0 = lt * 64;
    const int tid  = threadIdx.x;
    const int lane = tid & 31;
    const int w    = tid >> 5;
    const int wl   = w & 1;     // l half (32 rows)
    const int wm   = w >> 1;    // m quarter (32 cols of the 128-chunk)

    // ---- prefetch B chunk 0 into buf0 ----
    {
        const char* src = (const char*)(g_bh + ((size_t)(n*8 + 0) << 14));
        uint32_t dst = sb + 32768;
        #pragma unroll
        for (int i = 0; i < 8; i++)
            cp16(dst + (tid + i*256)*16, src + (tid + i*256)*16);
        CP_COMMIT();
    }

    // stage e_sq
    for (int i = tid; i < 1024; i += 256) esq_s[i] = g_esq[n*1024 + i];

    // stage + fp16-split A tile (swizzled): rows j = h (0..63), cols d
    for (int idx = tid; idx < 8192; idx += 256) {
        int d = idx >> 6, j = idx & 63;
        float v = x[(size_t)lt*65536 + (size_t)n*8192 + d*64 + j];
        __half h = __float2half_rn(v);
        __half l = __float2half_rn(v - __half2float(h));
        int elem = j*128 + (((d >> 3) ^ (j & 7)) << 3) + (d & 7);
        Ahi[elem] = h; Alo[elem] = l;
    }

    // ldmatrix per-lane address precompute
    const uint32_t sAh = sb, sBh0 = sb + 32768;
    const int q  = lane >> 3;
    const int r8 = lane & 7;
    const int cqA = q >> 1;
    const int cqB = q & 1;
    uint32_t aBase[2]; int a7[2];
    #pragma unroll
    for (int t2 = 0; t2 < 2; t2++) {
        int rowA = wl*32 + t2*16 + r8 + (q & 1)*8;
        aBase[t2] = sAh + rowA*256; a7[t2] = rowA & 7;
    }
    uint32_t bBase[2]; int b7[2];
    #pragma unroll
    for (int p = 0; p < 2; p++) {
        int rowB = wm*32 + p*16 + r8 + (q >> 1)*8;
        bBase[p] = sBh0 + rowB*256; b7[p] = rowB & 7;
    }

    float best[4], sec[4];
    int   idxm[4];
    #pragma unroll
    for (int s = 0; s < 4; s++) { best[s] = 3.4e38f; sec[s] = 3.4e38f; idxm[s] = 0; }

    const int col2 = (lane & 3) * 2;

    for (int mc = 0; mc < 8; mc++) {
        if (mc < 7) {
            const char* src = (const char*)(g_bh + ((size_t)(n*8 + mc + 1) << 14));
            uint32_t dbuf = sb + 32768 + (uint32_t)(((mc + 1) & 1) * 32768);
            #pragma unroll
            for (int i = 0; i < 8; i++)
                cp16(dbuf + (tid + i*256)*16, src + (tid + i*256)*16);
            CP_COMMIT();
            CP_WAIT(1);
        } else {
            CP_WAIT(0);
        }
        __syncthreads();

        const uint32_t bufOff = (uint32_t)((mc & 1) * 32768);

        float acc[2][4][4];
        #pragma unroll
        for (int t2 = 0; t2 < 2; t2++)
            #pragma unroll
            for (int mt = 0; mt < 4; mt++)
                #pragma unroll
                for (int c = 0; c < 4; c++) acc[t2][mt][c] = 0.f;

        #pragma unroll
        for (int ks = 0; ks < 8; ks++) {
            const int ks2 = ks * 2;
            uint32_t ah[2][4], al[2][4];
            #pragma unroll
            for (int t2 = 0; t2 < 2; t2++) {
                uint32_t off = (uint32_t)(((ks2 + cqA) ^ a7[t2]) << 4);
                ldsm4(ah[t2], aBase[t2] + off);
                ldsm4(al[t2], aBase[t2] + off + 16384);
            }
            uint32_t bh[2][4];
            #pragma unroll
            for (int p = 0; p < 2; p++) {
                uint32_t off = (uint32_t)(((ks2 + cqB) ^ b7[p]) << 4) + bufOff;
                ldsm4(bh[p], bBase[p] + off);
            }
            #pragma unroll
            for (int t2 = 0; t2 < 2; t2++)
                #pragma unroll
                for (int p = 0; p < 2; p++) {
                    mma_f16(acc[t2][2*p],   ah[t2], &bh[p][0]);
                    mma_f16(acc[t2][2*p+1], ah[t2], &bh[p][2]);
                    mma_f16(acc[t2][2*p],   al[t2], &bh[p][0]);
                    mma_f16(acc[t2][2*p+1], al[t2], &bh[p][2]);
                }
        }

        // epilogue: t = esq - acc/128  (acc = 256*dot; 2*dot = acc*2^-7)
        const int mbase = mc*128 + wm*32;
        #pragma unroll
        for (int t2 = 0; t2 < 2; t2++) {
            #pragma unroll
            for (int mt = 0; mt < 4; mt++) {
                float e0 = esq_s[mbase + mt*8 + col2];
                float e1 = esq_s[mbase + mt*8 + col2 + 1];
                int m0 = mbase + mt*8 + col2;
                {
                    int s = t2*2;
                    float ta = fmaf(acc[t2][mt][0], -0.0078125f, e0);
                    float tb = fmaf(acc[t2][mt][1], -0.0078125f, e1);
                    if (ta < best[s]) { sec[s] = best[s]; best[s] = ta; idxm[s] = m0; }
                    else if (ta < sec[s]) sec[s] = ta;
                    if (tb < best[s]) { sec[s] = best[s]; best[s] = tb; idxm[s] = m0 + 1; }
                    else if (tb < sec[s]) sec[s] = tb;
                }
                {
                    int s = t2*2 + 1;
                    float ta = fmaf(acc[t2][mt][2], -0.0078125f, e0);
                    float tb = fmaf(acc[t2][mt][3], -0.0078125f, e1);
                    if (ta < best[s]) { sec[s] = best[s]; best[s] = ta; idxm[s] = m0; }
                    else if (ta < sec[s]) sec[s] = ta;
                    if (tb < best[s]) { sec[s] = best[s]; best[s] = tb; idxm[s] = m0 + 1; }
                    else if (tb < sec[s]) sec[s] = tb;
                }
            }
        }
        __syncthreads();
    }

    // quad reduce (lanes sharing lane>>2 hold the same rows)
    #pragma unroll
    for (int s = 0; s < 4; s++) {
        float b = best[s], sc = sec[s];
        int   im = idxm[s];
        #pragma unroll
        for (int off = 1; off <= 2; off <<= 1) {
            float ob = __shfl_xor_sync(0xffffffffu, b,  off);
            float os = __shfl_xor_sync(0xffffffffu, sc, off);
            int   oi = __shfl_xor_sync(0xffffffffu, im, off);
            if (ob < b || (ob == b && oi < im)) {
                sc = fminf(b, os); b = ob; im = oi;
            } else {
                sc = fminf(sc, ob);
            }
        }
        best[s] = b; sec[s] = sc; idxm[s] = im;
    }
    if ((lane & 3) == 0) {
        const int g = lane >> 2;
        #pragma unroll
        for (int s = 0; s < 4; s++) {
            int row = wl*32 + (s >> 1)*16 + g + (s & 1)*8;
            sbest[wm*64 + row] = best[s];
            ssec [wm*64 + row] = sec[s];
            sidx [wm*64 + row] = idxm[s];
        }
    }
    __syncthreads();

    if (tid < 64) {
        float b = sbest[tid], s = ssec[tid];
        int   im = sidx[tid];
        #pragma unroll
        for (int qq = 1; qq < 4; qq++) {
            float bq = sbest[qq*64 + tid];
            float sq = ssec [qq*64 + tid];
            int   iq = sidx [qq*64 + tid];
            if (bq < b || (bq == b && iq < im)) { s = fminf(b, sq); b = bq; im = iq; }
            else { s = fminf(s, bq); }
        }
        int l = l0 + tid;
        int id = n*LPER + l;
        g_indices[id] = im;
        // rigorous per-row margin: 2^-9*sqrt(xsq*esqmax) + slack
        float mar = 0.001953125f * sqrtf(g_xsq[id] * __int_as_float(g_esqmaxb[n])) + 1.2e-4f;
        if (s - b < mar) {
            g_fixkey[id] = 0xFFFFFFFFFFFFFFFFull;
            int p = atomicAdd(&g_ucount, 1);
            g_ulist[p] = id;                 // id == (n<<14)|l
        }
    }
}

// ---------------- pass 2: batched exact rescan ----------------
// block = (n, mchunk of 128 codes, row-slice). Stage codes once, sweep rows.
__global__ void __launch_bounds__(128)
fixup_kernel(const float* __restrict__ x, const float* __restrict__ emb) {
    extern __shared__ float fsm[];
    float* E     = fsm;                 // [128 rows][stride 132]
    float* esq_c = fsm + 128*132;       // 128
    float* xs    = esq_c + 128;         // 128
    __shared__ unsigned long long wred[4];

    const int blk = blockIdx.x;
    const int n = blk >> 7, mc = (blk >> 4) & 7, slice = blk & 15;
    const int tid = threadIdx.x;

    // stage E chunk (float4 both sides; dest row stride 132 floats = 528B, 16B-aligned)
    const float4* src = (const float4*)(emb + ((size_t)n*1024 + mc*128)*128);
    for (int i = tid; i < 4096; i += 128) {
        int r = i >> 5, dq = i & 31;
        *(float4*)&E[r*132 + dq*4] = src[i];
    }
    esq_c[tid] = g_esq[n*1024 + mc*128 + tid];
    __syncthreads();

    const int cnt = g_ucount;
    for (int u = slice; u < cnt; u += 16) {
        int id = g_ulist[u];
        if ((id >> 14) != n) continue;
        int l = id & 16383;
        int b = l >> 6, h = l & 63;
        xs[tid] = x[(size_t)b*65536 + (size_t)n*8192 + tid*64 + h];
        __syncthreads();

        float xsq = g_xsq[id];
        const float* er = &E[tid*132];
        float c = 0.f;
        #pragma unroll 16
        for (int d = 0; d < 128; d++)          // ascending-d sequential chain (exact)
            c = fmaf(xs[d], er[d], c);
        float D = __fsub_rn(__fadd_rn(esq_c[tid], xsq), 2.f*c);

        // order-preserving pack: (ordered dist bits << 32) | m  -> min = argmin, lowest m on ties
        unsigned ud = __float_as_uint(D);
        ud = (ud & 0x80000000u) ? ~ud : (ud | 0x80000000u);
        unsigned long long key = ((unsigned long long)ud << 32) | (unsigned)(mc*128 + tid);
        #pragma unroll
        for (int o = 16; o; o >>= 1) {
            unsigned long long ok = __shfl_xor_sync(0xffffffffu, key, o);
            if (ok < key) key = ok;
        }
        if ((tid & 31) == 0) wred[tid >> 5] = key;
        __syncthreads();
        if (tid == 0) {
            unsigned long long k = wred[0];
            if (wred[1] < k) k = wred[1];
            if (wred[2] < k) k = wred[2];
            if (wred[3] < k) k = wred[3];
            atomicMin(&g_fixkey[id], k);
        }
        __syncthreads();
    }
}

// ---------------- unpack fixed indices ----------------
__global__ void unpack_kernel() {
    int cnt = g_ucount;
    for (int u = blockIdx.x*blockDim.x + threadIdx.x; u < cnt; u += gridDim.x*blockDim.x) {
        int id = g_ulist[u];
        g_indices[id] = (int)(unsigned)(g_fixkey[id] & 0xFFFFFFFFull);
    }
}

// ---------------- gather + z_q + loss partials + indices out ----------------
__global__ void __launch_bounds__(256)
gather_kernel(const float* __restrict__ x, const float* __restrict__ emb,
              float* __restrict__ out, float* __restrict__ out_idx, int write_extras) {
    __shared__ int   midx[64];
    __shared__ float rows[64*129];
    __shared__ float red[256];
    const int n = blockIdx.x & 7, b = blockIdx.x >> 3, tid = threadIdx.x;

    if (tid < 64) {
        int m = g_indices[n*LPER + b*HLAT + tid];
        midx[tid] = m;
        if (write_extras) out_idx[b*(NCB*HLAT) + n*HLAT + tid] = (float)m;
    }
    __syncthreads();
    for (int idx = tid; idx < 64*128; idx += 256) {
        int r = idx >> 7, d = idx & 127;
        rows[r*129 + d] = emb[(size_t)n*(MEMB*DEMB) + (size_t)midx[r]*DEMB + d];
    }
    __syncthreads();
    float s = 0.f;
    const size_t base = (size_t)b*65536 + (size_t)n*8192;
    for (int idx = tid; idx < 8192; idx += 256) {
        int d = idx >> 6, h = idx & 63;
        float q  = rows[h*129 + d];
        float xv = x[base + idx];
        out[base + idx] = q;
        float df = xv - q;
        s += df*df;
    }
    red[tid] = s;
    __syncthreads();
    for (int st = 128; st; st >>= 1) { if (tid < st) red[tid] += red[tid+st]; __syncthreads(); }
    if (tid == 0) g_part[blockIdx.x] = red[0];
}

// ---------------- entropy ----------------
__global__ void entropy_kernel() {
    __shared__ int   hist[MEMB];
    __shared__ float red[256];
    const int n = blockIdx.x, tid = threadIdx.x;
    for (int i = tid; i < MEMB; i += 256) hist[i] = 0;
    __syncthreads();
    for (int l = tid; l < LPER; l += 256) atomicAdd(&hist[g_indices[n*LPER + l]], 1);
    __syncthreads();
    float s = 0.f;
    for (int m = tid; m < MEMB; m += 256) {
        float p = (float)hist[m] * (1.f / (float)LPER);
        s += p * logf(p + 1e-10f);
    }
    red[tid] = s;
    __syncthreads();
    for (int st = 128; st; st >>= 1) { if (tid < st) red[tid] += red[tid+st]; __syncthreads(); }
    if (tid == 0) g_ent[n] = -red[0];
}

// ---------------- finalize ----------------
__global__ void finalize_kernel(float* __restrict__ out, int write_scalars) {
    __shared__ float red[256];
    const int tid = threadIdx.x;
    float s = 0.f;
    for (int i = tid; i < 2048; i += 256) s += g_part[i];
    red[tid] = s;
    __syncthreads();
    for (int st = 128; st; st >>= 1) { if (tid < st) red[tid] += red[tid+st]; __syncthreads(); }
    if (tid == 0 && write_scalars) {
        float loss = 0.25f * red[0] / (float)ZQ_ELEMS;
        float ent = 0.f, perp = 0.f;
        #pragma unroll
        for (int n = 0; n < NCB; n++) { ent += g_ent[n]; perp += expf(g_ent[n]); }
        out[ZQ_ELEMS + 0] = loss;
        out[ZQ_ELEMS + 1] = ent * (1.f / NCB);
        out[ZQ_ELEMS + 2] = perp * (1.f / NCB);
    }
}

// ---------------- launch ----------------
extern "C" void kernel_launch(void* const* d_in, const int* in_sizes, int n_in,
                              void* d_out, int out_size) {
    const float* x   = (const float*)d_in[0];
    const float* emb = (const float*)d_in[1];
    if (n_in >= 2 && in_sizes[0] == NCB*MEMB*DEMB && in_sizes[1] == ZQ_ELEMS) {
        const float* t = x; x = emb; emb = t;
    }
    float* out = (float*)d_out;
    const int full = (out_size >= ZQ_ELEMS + 3 + IDX_ELEMS) ? 1 : 0;

    const int SMEM_ARG = 105472 + 1024;
    cudaFuncSetAttribute(argmin_mma, cudaFuncAttributeMaxDynamicSharedMemorySize, SMEM_ARG);
    const int SMEM_FIX = (128*132 + 128 + 128) * 4;
    cudaFuncSetAttribute(fixup_kernel, cudaFuncAttributeMaxDynamicSharedMemorySize, SMEM_FIX);

    esq_kernel<<<(NCB*MEMB + 255)/256, 256>>>(emb);
    xsq_kernel<<<BATCH*NCB, 256>>>(x);
    bprep_kernel<<<(NCB*MEMB*DEMB + 255)/256, 256>>>(emb);
    argmin_mma<<<NCB * (LPER/64), 256, SMEM_ARG>>>(x);
    fixup_kernel<<<1024, 128, SMEM_FIX>>>(x, emb);
    unpack_kernel<<<64, 256>>>();
    gather_kernel<<<BATCH*NCB, 256>>>(x, emb, out, out + ZQ_ELEMS + 3, full);
    entropy_kernel<<<NCB, 256>>>();
    finalize_kernel<<<1, 256>>>(out, full);
}

// round 9
// speedup vs baseline: 1.0349x; 1.0349x over previous
#include <cuda_runtime.h>
#include <cuda_fp16.h>
#include <math.h>
#include <stdint.h>

#define NCB   8
#define MEMB  1024
#define DEMB  128
#define HLAT  64
#define BATCH 256
#define LPER  (BATCH*HLAT)              /* 16384 per codebook */
#define ZQ_ELEMS (BATCH*NCB*DEMB*HLAT)  /* 16777216 */
#define IDX_ELEMS (BATCH*NCB*HLAT)      /* 131072 */

// ---------------- device scratch ----------------
__device__ int   g_indices[NCB*LPER];
__device__ float g_esq[NCB*MEMB];
__device__ int   g_esqmaxb[NCB];          // max esq per codebook (float bits, >0)
__device__ float g_xsq[NCB*LPER];
__device__ float g_part[2048];
__device__ float g_ent[NCB];
__device__ int   g_ucount;
__device__ int   g_ulist[NCB*LPER];
__device__ unsigned long long g_fixkey[NCB*LPER];
__device__ float g_xpack[NCB*LPER*DEMB/8];   // packed x rows for flagged entries (cap 16384 rows)
// pre-swizzled fp16 embedding tiles (e*256): [n][mchunk 8][row 128][k 128]
__device__ __half g_bh[NCB*MEMB*DEMB];

#define XPACK_CAP (NCB*LPER/8)   /* 16384 rows — far above expected ~4k */

// ---------------- PTX helpers ----------------
__device__ __forceinline__ uint32_t smem_u32(const void* p) {
    uint32_t a;
    asm("{ .reg .u64 t; cvta.to.shared.u64 t, %1; cvt.u32.u64 %0, t; }" : "=r"(a) : "l"(p));
    return a;
}
__device__ __forceinline__ void ldsm4(uint32_t* r, uint32_t addr) {
    asm volatile("ldmatrix.sync.aligned.m8n8.x4.shared.b16 {%0,%1,%2,%3}, [%4];"
        : "=r"(r[0]), "=r"(r[1]), "=r"(r[2]), "=r"(r[3]) : "r"(addr));
}
__device__ __forceinline__ void mma_f16(float* c, const uint32_t* a, const uint32_t* b) {
    asm volatile("mma.sync.aligned.m16n8k16.row.col.f32.f16.f16.f32 "
        "{%0,%1,%2,%3}, {%4,%5,%6,%7}, {%8,%9}, {%0,%1,%2,%3};"
        : "+f"(c[0]), "+f"(c[1]), "+f"(c[2]), "+f"(c[3])
        : "r"(a[0]), "r"(a[1]), "r"(a[2]), "r"(a[3]), "r"(b[0]), "r"(b[1]));
}
__device__ __forceinline__ void cp16(uint32_t dst, const void* src) {
    asm volatile("cp.async.cg.shared.global [%0], [%1], 16;" :: "r"(dst), "l"(src) : "memory");
}
#define CP_COMMIT() asm volatile("cp.async.commit_group;" ::: "memory")
#define CP_WAIT(n)  asm volatile("cp.async.wait_group %0;" :: "n"(n) : "memory")

// ---------------- e_sq (exact sequential) + per-n max + ucount reset ----------------
__global__ void esq_kernel(const float* __restrict__ emb) {
    int t = blockIdx.x * blockDim.x + threadIdx.x;
    if (t == 0) g_ucount = 0;
    if (t >= NCB*MEMB) return;
    const float* row = emb + (size_t)t * DEMB;
    float acc = 0.f;
    #pragma unroll 8
    for (int d = 0; d < DEMB; d++) {
        float v = row[d];
        acc = __fadd_rn(acc, __fmul_rn(v, v));
    }
    g_esq[t] = acc;
    atomicMax(&g_esqmaxb[t >> 10], __float_as_int(acc));   // acc > 0
}

// ---------------- x_sq (exact sequential) ----------------
__global__ void __launch_bounds__(256)
xsq_kernel(const float* __restrict__ x) {
    __shared__ float tile[8192];
    const int n = blockIdx.x & 7, b = blockIdx.x >> 3, tid = threadIdx.x;
    const size_t base = (size_t)b*65536 + (size_t)n*8192;
    for (int i = tid; i < 8192; i += 256) tile[i] = x[base + i];
    __syncthreads();
    if (tid < 64) {
        float acc = 0.f;
        #pragma unroll 8
        for (int d = 0; d < DEMB; d++) {
            float v = tile[d*64 + tid];
            acc = __fadd_rn(acc, __fmul_rn(v, v));
        }
        g_xsq[n*LPER + b*HLAT + tid] = acc;
    }
}

// ---------------- embedding -> swizzled fp16 (e*256) tiles ----------------
__global__ void bprep_kernel(const float* __restrict__ emb) {
    int u = blockIdx.x * blockDim.x + threadIdx.x;
    if (u >= NCB*MEMB*DEMB) return;
    float v = emb[u] * 256.0f;               // exact scale
    int d = u & 127, m = (u >> 7) & 1023, n = u >> 17;
    int row = m & 127, mc = m >> 7;
    int elem = ((n*8 + mc)*128 + row)*128 + (((d >> 3) ^ (row & 7)) << 3) + (d & 7);
    g_bh[elem] = __float2half_rn(v);
}

// ---------------- pass 1: fp16 2-MMA approximate argmin ----------------
// CTA = (n, batch row). 256 threads = 8 warps = 2(l) x 4(m); warp tile 32x32.
// m-chunks of 128 codes (8 iters), B double-buffered via cp.async.
// acc = (Xhi + Xlo) . (256*E)_f16 ; dist_proxy = esq - acc/128.
__global__ void __launch_bounds__(256, 2)
argmin_mma(const float* __restrict__ x) {
    extern __shared__ char smraw[];
    uint32_t sraw = smem_u32(smraw);
    uint32_t sb = (sraw + 1023u) & ~1023u;
    char* sm = smraw + (sb - sraw);
    __half* Ahi = (__half*)(sm);              // 16KB @0
    __half* Alo = (__half*)(sm + 16384);      // 16KB
    // B buffers: buf0 @32768 (32KB), buf1 @65536 (32KB)
    float* esq_s = (float*)(sm + 98304);      // 4KB
    float* sbest = (float*)(sm + 102400);     // 256 f32
    float* ssec  = (float*)(sm + 103424);     // 256 f32
    int*   sidx  = (int*)  (sm + 104448);     // 256 int

    const int n  = blockIdx.x >> 8;
    const int lt = blockIdx.x & 255;          // batch row b
    const int l0 = lt * 64;
    const int tid  = threadIdx.x;
    const int lane = tid & 31;
    const int w    = tid >> 5;
    const int wl   = w & 1;     // l half (32 rows)
    const int wm   = w >> 1;    // m quarter (32 cols of the 128-chunk)

    // ---- prefetch B chunk 0 into buf0 ----
    {
        const char* src = (const char*)(g_bh + ((size_t)(n*8 + 0) << 14));
        uint32_t dst = sb + 32768;
        #pragma unroll
        for (int i = 0; i < 8; i++)
            cp16(dst + (tid + i*256)*16, src + (tid + i*256)*16);
        CP_COMMIT();
    }

    // stage e_sq
    for (int i = tid; i < 1024; i += 256) esq_s[i] = g_esq[n*1024 + i];

    // stage + fp16-split A tile (swizzled): rows j = h (0..63), cols d
    for (int idx = tid; idx < 8192; idx += 256) {
        int d = idx >> 6, j = idx & 63;
        float v = x[(size_t)lt*65536 + (size_t)n*8192 + d*64 + j];
        __half h = __float2half_rn(v);
        __half l = __float2half_rn(v - __half2float(h));
        int elem = j*128 + (((d >> 3) ^ (j & 7)) << 3) + (d & 7);
        Ahi[elem] = h; Alo[elem] = l;
    }

    // ldmatrix per-lane address precompute
    const uint32_t sAh = sb, sBh0 = sb + 32768;
    const int q  = lane >> 3;
    const int r8 = lane & 7;
    const int cqA = q >> 1;
    const int cqB = q & 1;
    uint32_t aBase[2]; int a7[2];
    #pragma unroll
    for (int t2 = 0; t2 < 2; t2++) {
        int rowA = wl*32 + t2*16 + r8 + (q & 1)*8;
        aBase[t2] = sAh + rowA*256; a7[t2] = rowA & 7;
    }
    uint32_t bBase[2]; int b7[2];
    #pragma unroll
    for (int p = 0; p < 2; p++) {
        int rowB = wm*32 + p*16 + r8 + (q >> 1)*8;
        bBase[p] = sBh0 + rowB*256; b7[p] = rowB & 7;
    }

    float best[4], sec[4];
    int   idxm[4];
    #pragma unroll
    for (int s = 0; s < 4; s++) { best[s] = 3.4e38f; sec[s] = 3.4e38f; idxm[s] = 0; }

    const int col2 = (lane & 3) * 2;

    for (int mc = 0; mc < 8; mc++) {
        if (mc < 7) {
            const char* src = (const char*)(g_bh + ((size_t)(n*8 + mc + 1) << 14));
            uint32_t dbuf = sb + 32768 + (uint32_t)(((mc + 1) & 1) * 32768);
            #pragma unroll
            for (int i = 0; i < 8; i++)
                cp16(dbuf + (tid + i*256)*16, src + (tid + i*256)*16);
            CP_COMMIT();
            CP_WAIT(1);
        } else {
            CP_WAIT(0);
        }
        __syncthreads();

        const uint32_t bufOff = (uint32_t)((mc & 1) * 32768);

        float acc[2][4][4];
        #pragma unroll
        for (int t2 = 0; t2 < 2; t2++)
            #pragma unroll
            for (int mt = 0; mt < 4; mt++)
                #pragma unroll
                for (int c = 0; c < 4; c++) acc[t2][mt][c] = 0.f;

        #pragma unroll
        for (int ks = 0; ks < 8; ks++) {
            const int ks2 = ks * 2;
            uint32_t ah[2][4], al[2][4];
            #pragma unroll
            for (int t2 = 0; t2 < 2; t2++) {
                uint32_t off = (uint32_t)(((ks2 + cqA) ^ a7[t2]) << 4);
                ldsm4(ah[t2], aBase[t2] + off);
                ldsm4(al[t2], aBase[t2] + off + 16384);
            }
            uint32_t bh[2][4];
            #pragma unroll
            for (int p = 0; p < 2; p++) {
                uint32_t off = (uint32_t)(((ks2 + cqB) ^ b7[p]) << 4) + bufOff;
                ldsm4(bh[p], bBase[p] + off);
            }
            #pragma unroll
            for (int t2 = 0; t2 < 2; t2++)
                #pragma unroll
                for (int p = 0; p < 2; p++) {
                    mma_f16(acc[t2][2*p],   ah[t2], &bh[p][0]);
                    mma_f16(acc[t2][2*p+1], ah[t2], &bh[p][2]);
                    mma_f16(acc[t2][2*p],   al[t2], &bh[p][0]);
                    mma_f16(acc[t2][2*p+1], al[t2], &bh[p][2]);
                }
        }

        // epilogue: t = esq - acc/128  (acc = 256*dot; 2*dot = acc*2^-7)
        const int mbase = mc*128 + wm*32;
        #pragma unroll
        for (int t2 = 0; t2 < 2; t2++) {
            #pragma unroll
            for (int mt = 0; mt < 4; mt++) {
                float e0 = esq_s[mbase + mt*8 + col2];
                float e1 = esq_s[mbase + mt*8 + col2 + 1];
                int m0 = mbase + mt*8 + col2;
                {
                    int s = t2*2;
                    float ta = fmaf(acc[t2][mt][0], -0.0078125f, e0);
                    float tb = fmaf(acc[t2][mt][1], -0.0078125f, e1);
                    if (ta < best[s]) { sec[s] = best[s]; best[s] = ta; idxm[s] = m0; }
                    else if (ta < sec[s]) sec[s] = ta;
                    if (tb < best[s]) { sec[s] = best[s]; best[s] = tb; idxm[s] = m0 + 1; }
                    else if (tb < sec[s]) sec[s] = tb;
                }
                {
                    int s = t2*2 + 1;
                    float ta = fmaf(acc[t2][mt][2], -0.0078125f, e0);
                    float tb = fmaf(acc[t2][mt][3], -0.0078125f, e1);
                    if (ta < best[s]) { sec[s] = best[s]; best[s] = ta; idxm[s] = m0; }
                    else if (ta < sec[s]) sec[s] = ta;
                    if (tb < best[s]) { sec[s] = best[s]; best[s] = tb; idxm[s] = m0 + 1; }
                    else if (tb < sec[s]) sec[s] = tb;
                }
            }
        }
        __syncthreads();
    }

    // quad reduce (lanes sharing lane>>2 hold the same rows)
    #pragma unroll
    for (int s = 0; s < 4; s++) {
        float b = best[s], sc = sec[s];
        int   im = idxm[s];
        #pragma unroll
        for (int off = 1; off <= 2; off <<= 1) {
            float ob = __shfl_xor_sync(0xffffffffu, b,  off);
            float os = __shfl_xor_sync(0xffffffffu, sc, off);
            int   oi = __shfl_xor_sync(0xffffffffu, im, off);
            if (ob < b || (ob == b && oi < im)) {
                sc = fminf(b, os); b = ob; im = oi;
            } else {
                sc = fminf(sc, ob);
            }
        }
        best[s] = b; sec[s] = sc; idxm[s] = im;
    }
    if ((lane & 3) == 0) {
        const int g = lane >> 2;
        #pragma unroll
        for (int s = 0; s < 4; s++) {
            int row = wl*32 + (s >> 1)*16 + g + (s & 1)*8;
            sbest[wm*64 + row] = best[s];
            ssec [wm*64 + row] = sec[s];
            sidx [wm*64 + row] = idxm[s];
        }
    }
    __syncthreads();

    if (tid < 64) {
        float b = sbest[tid], s = ssec[tid];
        int   im = sidx[tid];
        #pragma unroll
        for (int qq = 1; qq < 4; qq++) {
            float bq = sbest[qq*64 + tid];
            float sq = ssec [qq*64 + tid];
            int   iq = sidx [qq*64 + tid];
            if (bq < b || (bq == b && iq < im)) { s = fminf(b, sq); b = bq; im = iq; }
            else { s = fminf(s, bq); }
        }
        int l = l0 + tid;
        int id = n*LPER + l;
        g_indices[id] = im;
        // rigorous per-row margin: 2^-9*sqrt(xsq*esqmax) + slack
        float mar = 0.001953125f * sqrtf(g_xsq[id] * __int_as_float(g_esqmaxb[n])) + 1.2e-4f;
        if (s - b < mar) {
            g_fixkey[id] = 0xFFFFFFFFFFFFFFFFull;
            int p = atomicAdd(&g_ucount, 1);
            if (p < XPACK_CAP) g_ulist[p] = id;   // id == (n<<14)|l
        }
    }
}

// ---------------- pack flagged x rows (one strided gather per row) ----------------
__global__ void __launch_bounds__(128)
pack_kernel(const float* __restrict__ x) {
    int cnt = g_ucount; if (cnt > XPACK_CAP) cnt = XPACK_CAP;
    for (int u = blockIdx.x; u < cnt; u += gridDim.x) {
        int id = g_ulist[u];
        int n = id >> 14, l = id & 16383;
        int b = l >> 6, h = l & 63;
        g_xpack[(size_t)u*128 + threadIdx.x] =
            x[(size_t)b*65536 + (size_t)n*8192 + threadIdx.x*64 + h];
    }
}

// ---------------- pass 2: batched exact rescan (conflict-free, coalesced) ----------------
// block = (n, mchunk of 128 codes, row-slice of 16). E staged stride-129; xs from g_xpack.
__global__ void __launch_bounds__(128)
fixup_kernel(const float* __restrict__ emb) {
    extern __shared__ float fsm[];
    float* E     = fsm;                 // [128 codes][stride 129]
    float* esq_c = fsm + 128*129;       // 128
    float* xs    = esq_c + 128;         // 128
    __shared__ unsigned long long wred[4];

    const int blk = blockIdx.x;
    const int n = blk >> 7, mc = (blk >> 4) & 7, slice = blk & 15;
    const int tid = threadIdx.x;

    // stage E chunk: read float4, scatter to stride-129 rows (bank-conflict-free dot reads)
    const float4* src = (const float4*)(emb + ((size_t)n*1024 + mc*128)*128);
    for (int i = tid; i < 4096; i += 128) {
        int r = i >> 5, dq = (i & 31) * 4;
        float4 v = src[i];
        float* dst = &E[r*129 + dq];
        dst[0] = v.x; dst[1] = v.y; dst[2] = v.z; dst[3] = v.w;
    }
    esq_c[tid] = g_esq[n*1024 + mc*128 + tid];
    __syncthreads();

    int cnt = g_ucount; if (cnt > XPACK_CAP) cnt = XPACK_CAP;
    for (int u = slice; u < cnt; u += 16) {
        int id = g_ulist[u];
        if ((id >> 14) != n) continue;
        xs[tid] = g_xpack[(size_t)u*128 + tid];          // coalesced 512B
        __syncthreads();

        float xsq = g_xsq[id];
        const float* er = &E[tid*129];
        float c = 0.f;
        #pragma unroll 16
        for (int d = 0; d < 128; d++)          // ascending-d sequential chain (exact)
            c = fmaf(xs[d], er[d], c);
        float D = __fsub_rn(__fadd_rn(esq_c[tid], xsq), 2.f*c);

        // order-preserving pack: (ordered dist bits << 32) | m -> min = argmin, lowest m on ties
        unsigned ud = __float_as_uint(D);
        ud = (ud & 0x80000000u) ? ~ud : (ud | 0x80000000u);
        unsigned long long key = ((unsigned long long)ud << 32) | (unsigned)(mc*128 + tid);
        #pragma unroll
        for (int o = 16; o; o >>= 1) {
            unsigned long long ok = __shfl_xor_sync(0xffffffffu, key, o);
            if (ok < key) key = ok;
        }
        if ((tid & 31) == 0) wred[tid >> 5] = key;
        __syncthreads();
        if (tid == 0) {
            unsigned long long k = wred[0];
            if (wred[1] < k) k = wred[1];
            if (wred[2] < k) k = wred[2];
            if (wred[3] < k) k = wred[3];
            atomicMin(&g_fixkey[id], k);
        }
        __syncthreads();
    }
}

// ---------------- unpack fixed indices ----------------
__global__ void unpack_kernel() {
    int cnt = g_ucount; if (cnt > XPACK_CAP) cnt = XPACK_CAP;
    for (int u = blockIdx.x*blockDim.x + threadIdx.x; u < cnt; u += gridDim.x*blockDim.x) {
        int id = g_ulist[u];
        g_indices[id] = (int)(unsigned)(g_fixkey[id] & 0xFFFFFFFFull);
    }
}

// ---------------- gather + z_q + loss partials + indices out ----------------
__global__ void __launch_bounds__(256)
gather_kernel(const float* __restrict__ x, const float* __restrict__ emb,
              float* __restrict__ out, float* __restrict__ out_idx, int write_extras) {
    __shared__ int   midx[64];
    __shared__ float rows[64*129];
    __shared__ float red[256];
    const int n = blockIdx.x & 7, b = blockIdx.x >> 3, tid = threadIdx.x;

    if (tid < 64) {
        int m = g_indices[n*LPER + b*HLAT + tid];
        midx[tid] = m;
        if (write_extras) out_idx[b*(NCB*HLAT) + n*HLAT + tid] = (float)m;
    }
    __syncthreads();
    for (int idx = tid; idx < 64*128; idx += 256) {
        int r = idx >> 7, d = idx & 127;
        rows[r*129 + d] = emb[(size_t)n*(MEMB*DEMB) + (size_t)midx[r]*DEMB + d];
    }
    __syncthreads();
    float s = 0.f;
    const size_t base = (size_t)b*65536 + (size_t)n*8192;
    for (int idx = tid; idx < 8192; idx += 256) {
        int d = idx >> 6, h = idx & 63;
        float q  = rows[h*129 + d];
        float xv = x[base + idx];
        out[base + idx] = q;
        float df = xv - q;
        s += df*df;
    }
    red[tid] = s;
    __syncthreads();
    for (int st = 128; st; st >>= 1) { if (tid < st) red[tid] += red[tid+st]; __syncthreads(); }
    if (tid == 0) g_part[blockIdx.x] = red[0];
}

// ---------------- entropy ----------------
__global__ void entropy_kernel() {
    __shared__ int   hist[MEMB];
    __shared__ float red[256];
    const int n = blockIdx.x, tid = threadIdx.x;
    for (int i = tid; i < MEMB; i += 256) hist[i] = 0;
    __syncthreads();
    for (int l = tid; l < LPER; l += 256) atomicAdd(&hist[g_indices[n*LPER + l]], 1);
    __syncthreads();
    float s = 0.f;
    for (int m = tid; m < MEMB; m += 256) {
        float p = (float)hist[m] * (1.f / (float)LPER);
        s += p * logf(p + 1e-10f);
    }
    red[tid] = s;
    __syncthreads();
    for (int st = 128; st; st >>= 1) { if (tid < st) red[tid] += red[tid+st]; __syncthreads(); }
    if (tid == 0) g_ent[n] = -red[0];
}

// ---------------- finalize ----------------
__global__ void finalize_kernel(float* __restrict__ out, int write_scalars) {
    __shared__ float red[256];
    const int tid = threadIdx.x;
    float s = 0.f;
    for (int i = tid; i < 2048; i += 256) s += g_part[i];
    red[tid] = s;
    __syncthreads();
    for (int st = 128; st; st >>= 1) { if (tid < st) red[tid] += red[tid+st]; __syncthreads(); }
    if (tid == 0 && write_scalars) {
        float loss = 0.25f * red[0] / (float)ZQ_ELEMS;
        float ent = 0.f, perp = 0.f;
        #pragma unroll
        for (int n = 0; n < NCB; n++) { ent += g_ent[n]; perp += expf(g_ent[n]); }
        out[ZQ_ELEMS + 0] = loss;
        out[ZQ_ELEMS + 1] = ent * (1.f / NCB);
        out[ZQ_ELEMS + 2] = perp * (1.f / NCB);
    }
}

// ---------------- launch ----------------
extern "C" void kernel_launch(void* const* d_in, const int* in_sizes, int n_in,
                              void* d_out, int out_size) {
    const float* x   = (const float*)d_in[0];
    const float* emb = (const float*)d_in[1];
    if (n_in >= 2 && in_sizes[0] == NCB*MEMB*DEMB && in_sizes[1] == ZQ_ELEMS) {
        const float* t = x; x = emb; emb = t;
    }
    float* out = (float*)d_out;
    const int full = (out_size >= ZQ_ELEMS + 3 + IDX_ELEMS) ? 1 : 0;

    const int SMEM_ARG = 105472 + 1024;
    cudaFuncSetAttribute(argmin_mma, cudaFuncAttributeMaxDynamicSharedMemorySize, SMEM_ARG);
    const int SMEM_FIX = (128*129 + 128 + 128) * 4;
    cudaFuncSetAttribute(fixup_kernel, cudaFuncAttributeMaxDynamicSharedMemorySize, SMEM_FIX);

    esq_kernel<<<(NCB*MEMB + 255)/256, 256>>>(emb);
    xsq_kernel<<<BATCH*NCB, 256>>>(x);
    bprep_kernel<<<(NCB*MEMB*DEMB + 255)/256, 256>>>(emb);
    argmin_mma<<<NCB * (LPER/64), 256, SMEM_ARG>>>(x);
    pack_kernel<<<2048, 128>>>(x);
    fixup_kernel<<<1024, 128, SMEM_FIX>>>(emb);
    unpack_kernel<<<64, 256>>>();
    gather_kernel<<<BATCH*NCB, 256>>>(x, emb, out, out + ZQ_ELEMS + 3, full);
    entropy_kernel<<<NCB, 256>>>();
    finalize_kernel<<<1, 256>>>(out, full);
}

// round 10
// speedup vs baseline: 1.5586x; 1.5060x over previous
#include <cuda_runtime.h>
#include <cuda_fp16.h>
#include <math.h>
#include <stdint.h>

#define NCB   8
#define MEMB  1024
#define DEMB  128
#define HLAT  64
#define BATCH 256
#define LPER  (BATCH*HLAT)              /* 16384 per codebook */
#define ZQ_ELEMS (BATCH*NCB*DEMB*HLAT)  /* 16777216 */
#define IDX_ELEMS (BATCH*NCB*HLAT)      /* 131072 */

// ---------------- device scratch ----------------
__device__ int   g_indices[NCB*LPER];
__device__ float g_esq[NCB*MEMB];
__device__ int   g_esqmaxb[NCB];          // max esq per codebook (float bits, >0)
__device__ float g_xsq[NCB*LPER];
__device__ float g_part[2048];
__device__ float g_ent[NCB];
__device__ int   g_ucnt[NCB];             // per-codebook uncertain counts
__device__ int   g_ulistn[NCB*LPER];      // per-codebook lists of l values
__device__ unsigned long long g_fixkey[NCB*LPER];
// pre-swizzled fp16 embedding tiles (e*256): [n][mchunk 8][row 128][k 128]
__device__ __half g_bh[NCB*MEMB*DEMB];

// ---------------- PTX helpers ----------------
__device__ __forceinline__ uint32_t smem_u32(const void* p) {
    uint32_t a;
    asm("{ .reg .u64 t; cvta.to.shared.u64 t, %1; cvt.u32.u64 %0, t; }" : "=r"(a) : "l"(p));
    return a;
}
__device__ __forceinline__ void ldsm4(uint32_t* r, uint32_t addr) {
    asm volatile("ldmatrix.sync.aligned.m8n8.x4.shared.b16 {%0,%1,%2,%3}, [%4];"
        : "=r"(r[0]), "=r"(r[1]), "=r"(r[2]), "=r"(r[3]) : "r"(addr));
}
__device__ __forceinline__ void mma_f16(float* c, const uint32_t* a, const uint32_t* b) {
    asm volatile("mma.sync.aligned.m16n8k16.row.col.f32.f16.f16.f32 "
        "{%0,%1,%2,%3}, {%4,%5,%6,%7}, {%8,%9}, {%0,%1,%2,%3};"
        : "+f"(c[0]), "+f"(c[1]), "+f"(c[2]), "+f"(c[3])
        : "r"(a[0]), "r"(a[1]), "r"(a[2]), "r"(a[3]), "r"(b[0]), "r"(b[1]));
}
__device__ __forceinline__ void cp16(uint32_t dst, const void* src) {
    asm volatile("cp.async.cg.shared.global [%0], [%1], 16;" :: "r"(dst), "l"(src) : "memory");
}
#define CP_COMMIT() asm volatile("cp.async.commit_group;" ::: "memory")
#define CP_WAIT(n)  asm volatile("cp.async.wait_group %0;" :: "n"(n) : "memory")

// ---------------- e_sq (exact sequential) + per-n max + count reset ----------------
__global__ void esq_kernel(const float* __restrict__ emb) {
    int t = blockIdx.x * blockDim.x + threadIdx.x;
    if (t < NCB) g_ucnt[t] = 0;
    if (t >= NCB*MEMB) return;
    const float* row = emb + (size_t)t * DEMB;
    float acc = 0.f;
    #pragma unroll 8
    for (int d = 0; d < DEMB; d++) {
        float v = row[d];
        acc = __fadd_rn(acc, __fmul_rn(v, v));
    }
    g_esq[t] = acc;
    atomicMax(&g_esqmaxb[t >> 10], __float_as_int(acc));   // acc > 0
}

// ---------------- x_sq (exact sequential) ----------------
__global__ void __launch_bounds__(256)
xsq_kernel(const float* __restrict__ x) {
    __shared__ float tile[8192];
    const int n = blockIdx.x & 7, b = blockIdx.x >> 3, tid = threadIdx.x;
    const size_t base = (size_t)b*65536 + (size_t)n*8192;
    for (int i = tid; i < 8192; i += 256) tile[i] = x[base + i];
    __syncthreads();
    if (tid < 64) {
        float acc = 0.f;
        #pragma unroll 8
        for (int d = 0; d < DEMB; d++) {
            float v = tile[d*64 + tid];
            acc = __fadd_rn(acc, __fmul_rn(v, v));
        }
        g_xsq[n*LPER + b*HLAT + tid] = acc;
    }
}

// ---------------- embedding -> swizzled fp16 (e*256) tiles ----------------
__global__ void bprep_kernel(const float* __restrict__ emb) {
    int u = blockIdx.x * blockDim.x + threadIdx.x;
    if (u >= NCB*MEMB*DEMB) return;
    float v = emb[u] * 256.0f;               // exact scale
    int d = u & 127, m = (u >> 7) & 1023, n = u >> 17;
    int row = m & 127, mc = m >> 7;
    int elem = ((n*8 + mc)*128 + row)*128 + (((d >> 3) ^ (row & 7)) << 3) + (d & 7);
    g_bh[elem] = __float2half_rn(v);
}

// ---------------- pass 1: fp16 2-MMA approximate argmin ----------------
__global__ void __launch_bounds__(256, 2)
argmin_mma(const float* __restrict__ x) {
    extern __shared__ char smraw[];
    uint32_t sraw = smem_u32(smraw);
    uint32_t sb = (sraw + 1023u) & ~1023u;
    char* sm = smraw + (sb - sraw);
    __half* Ahi = (__half*)(sm);              // 16KB @0
    __half* Alo = (__half*)(sm + 16384);      // 16KB
    // B buffers: buf0 @32768 (32KB), buf1 @65536 (32KB)
    float* esq_s = (float*)(sm + 98304);      // 4KB
    float* sbest = (float*)(sm + 102400);     // 256 f32
    float* ssec  = (float*)(sm + 103424);     // 256 f32
    int*   sidx  = (int*)  (sm + 104448);     // 256 int

    const int n  = blockIdx.x >> 8;
    const int lt = blockIdx.x & 255;          // batch row b
    const int l0 = lt * 64;
    const int tid  = threadIdx.x;
    const int lane = tid & 31;
    const int w    = tid >> 5;
    const int wl   = w & 1;     // l half (32 rows)
    const int wm   = w >> 1;    // m quarter (32 cols of the 128-chunk)

    // ---- prefetch B chunk 0 into buf0 ----
    {
        const char* src = (const char*)(g_bh + ((size_t)(n*8 + 0) << 14));
        uint32_t dst = sb + 32768;
        #pragma unroll
        for (int i = 0; i < 8; i++)
            cp16(dst + (tid + i*256)*16, src + (tid + i*256)*16);
        CP_COMMIT();
    }

    // stage e_sq
    for (int i = tid; i < 1024; i += 256) esq_s[i] = g_esq[n*1024 + i];

    // stage + fp16-split A tile (swizzled): rows j = h (0..63), cols d
    for (int idx = tid; idx < 8192; idx += 256) {
        int d = idx >> 6, j = idx & 63;
        float v = x[(size_t)lt*65536 + (size_t)n*8192 + d*64 + j];
        __half h = __float2half_rn(v);
        __half l = __float2half_rn(v - __half2float(h));
        int elem = j*128 + (((d >> 3) ^ (j & 7)) << 3) + (d & 7);
        Ahi[elem] = h; Alo[elem] = l;
    }

    // ldmatrix per-lane address precompute
    const uint32_t sAh = sb, sBh0 = sb + 32768;
    const int q  = lane >> 3;
    const int r8 = lane & 7;
    const int cqA = q >> 1;
    const int cqB = q & 1;
    uint32_t aBase[2]; int a7[2];
    #pragma unroll
    for (int t2 = 0; t2 < 2; t2++) {
        int rowA = wl*32 + t2*16 + r8 + (q & 1)*8;
        aBase[t2] = sAh + rowA*256; a7[t2] = rowA & 7;
    }
    uint32_t bBase[2]; int b7[2];
    #pragma unroll
    for (int p = 0; p < 2; p++) {
        int rowB = wm*32 + p*16 + r8 + (q >> 1)*8;
        bBase[p] = sBh0 + rowB*256; b7[p] = rowB & 7;
    }

    float best[4], sec[4];
    int   idxm[4];
    #pragma unroll
    for (int s = 0; s < 4; s++) { best[s] = 3.4e38f; sec[s] = 3.4e38f; idxm[s] = 0; }

    const int col2 = (lane & 3) * 2;

    for (int mc = 0; mc < 8; mc++) {
        if (mc < 7) {
            const char* src = (const char*)(g_bh + ((size_t)(n*8 + mc + 1) << 14));
            uint32_t dbuf = sb + 32768 + (uint32_t)(((mc + 1) & 1) * 32768);
            #pragma unroll
            for (int i = 0; i < 8; i++)
                cp16(dbuf + (tid + i*256)*16, src + (tid + i*256)*16);
            CP_COMMIT();
            CP_WAIT(1);
        } else {
            CP_WAIT(0);
        }
        __syncthreads();

        const uint32_t bufOff = (uint32_t)((mc & 1) * 32768);

        float acc[2][4][4];
        #pragma unroll
        for (int t2 = 0; t2 < 2; t2++)
            #pragma unroll
            for (int mt = 0; mt < 4; mt++)
                #pragma unroll
                for (int c = 0; c < 4; c++) acc[t2][mt][c] = 0.f;

        #pragma unroll
        for (int ks = 0; ks < 8; ks++) {
            const int ks2 = ks * 2;
            uint32_t ah[2][4], al[2][4];
            #pragma unroll
            for (int t2 = 0; t2 < 2; t2++) {
                uint32_t off = (uint32_t)(((ks2 + cqA) ^ a7[t2]) << 4);
                ldsm4(ah[t2], aBase[t2] + off);
                ldsm4(al[t2], aBase[t2] + off + 16384);
            }
            uint32_t bh[2][4];
            #pragma unroll
            for (int p = 0; p < 2; p++) {
                uint32_t off = (uint32_t)(((ks2 + cqB) ^ b7[p]) << 4) + bufOff;
                ldsm4(bh[p], bBase[p] + off);
            }
            #pragma unroll
            for (int t2 = 0; t2 < 2; t2++)
                #pragma unroll
                for (int p = 0; p < 2; p++) {
                    mma_f16(acc[t2][2*p],   ah[t2], &bh[p][0]);
                    mma_f16(acc[t2][2*p+1], ah[t2], &bh[p][2]);
                    mma_f16(acc[t2][2*p],   al[t2], &bh[p][0]);
                    mma_f16(acc[t2][2*p+1], al[t2], &bh[p][2]);
                }
        }

        // epilogue: t = esq - acc/128  (acc = 256*dot; 2*dot = acc*2^-7)
        const int mbase = mc*128 + wm*32;
        #pragma unroll
        for (int t2 = 0; t2 < 2; t2++) {
            #pragma unroll
            for (int mt = 0; mt < 4; mt++) {
                float e0 = esq_s[mbase + mt*8 + col2];
                float e1 = esq_s[mbase + mt*8 + col2 + 1];
                int m0 = mbase + mt*8 + col2;
                {
                    int s = t2*2;
                    float ta = fmaf(acc[t2][mt][0], -0.0078125f, e0);
                    float tb = fmaf(acc[t2][mt][1], -0.0078125f, e1);
                    if (ta < best[s]) { sec[s] = best[s]; best[s] = ta; idxm[s] = m0; }
                    else if (ta < sec[s]) sec[s] = ta;
                    if (tb < best[s]) { sec[s] = best[s]; best[s] = tb; idxm[s] = m0 + 1; }
                    else if (tb < sec[s]) sec[s] = tb;
                }
                {
                    int s = t2*2 + 1;
                    float ta = fmaf(acc[t2][mt][2], -0.0078125f, e0);
                    float tb = fmaf(acc[t2][mt][3], -0.0078125f, e1);
                    if (ta < best[s]) { sec[s] = best[s]; best[s] = ta; idxm[s] = m0; }
                    else if (ta < sec[s]) sec[s] = ta;
                    if (tb < best[s]) { sec[s] = best[s]; best[s] = tb; idxm[s] = m0 + 1; }
                    else if (tb < sec[s]) sec[s] = tb;
                }
            }
        }
        __syncthreads();
    }

    // quad reduce (lanes sharing lane>>2 hold the same rows)
    #pragma unroll
    for (int s = 0; s < 4; s++) {
        float b = best[s], sc = sec[s];
        int   im = idxm[s];
        #pragma unroll
        for (int off = 1; off <= 2; off <<= 1) {
            float ob = __shfl_xor_sync(0xffffffffu, b,  off);
            float os = __shfl_xor_sync(0xffffffffu, sc, off);
            int   oi = __shfl_xor_sync(0xffffffffu, im, off);
            if (ob < b || (ob == b && oi < im)) {
                sc = fminf(b, os); b = ob; im = oi;
            } else {
                sc = fminf(sc, ob);
            }
        }
        best[s] = b; sec[s] = sc; idxm[s] = im;
    }
    if ((lane & 3) == 0) {
        const int g = lane >> 2;
        #pragma unroll
        for (int s = 0; s < 4; s++) {
            int row = wl*32 + (s >> 1)*16 + g + (s & 1)*8;
            sbest[wm*64 + row] = best[s];
            ssec [wm*64 + row] = sec[s];
            sidx [wm*64 + row] = idxm[s];
        }
    }
    __syncthreads();

    if (tid < 64) {
        float b = sbest[tid], s = ssec[tid];
        int   im = sidx[tid];
        #pragma unroll
        for (int qq = 1; qq < 4; qq++) {
            float bq = sbest[qq*64 + tid];
            float sq = ssec [qq*64 + tid];
            int   iq = sidx [qq*64 + tid];
            if (bq < b || (bq == b && iq < im)) { s = fminf(b, sq); b = bq; im = iq; }
            else { s = fminf(s, bq); }
        }
        int l = l0 + tid;
        int id = n*LPER + l;
        g_indices[id] = im;
        // rigorous per-row margin: 2^-9*sqrt(xsq*esqmax) + slack
        float mar = 0.001953125f * sqrtf(g_xsq[id] * __int_as_float(g_esqmaxb[n])) + 1.2e-4f;
        if (s - b < mar) {
            g_fixkey[id] = 0xFFFFFFFFFFFFFFFFull;
            int p = atomicAdd(&g_ucnt[n], 1);
            g_ulistn[n*LPER + p] = l;
        }
    }
}

// ---------------- pass 2: batched exact rescan v5 ----------------
// block = (n, mchunk of 128 codes, slice of 16). 128 threads = one code each;
// each visit processes 8 rows: E read once per code, 8 exact fmaf chains.
__global__ void __launch_bounds__(128)
fixup_kernel(const float* __restrict__ x, const float* __restrict__ emb) {
    extern __shared__ float fsm[];
    float* E     = fsm;                       // [128 codes][stride 132]
    float* xs    = fsm + 128*132;             // [8 rows][128]
    float* esq_c = xs + 1024;                 // [128]
    float* xsq_s = esq_c + 128;               // [8]
    unsigned long long* wred = (unsigned long long*)(xsq_s + 8);   // [4 warps][8 rows]

    const int n     = blockIdx.x >> 7;
    const int mc    = (blockIdx.x >> 4) & 7;
    const int slice = blockIdx.x & 15;
    const int tid   = threadIdx.x;            // code within chunk
    const int wid   = tid >> 5, lane = tid & 31;

    // stage E chunk (reads coalesced; row stride 132 words -> conflict-free LDS.128)
    const float* src = emb + ((size_t)n*1024 + mc*128)*128;
    for (int i = tid; i < 16384; i += 128) {
        int r = i >> 7, d = i & 127;
        E[r*132 + d] = src[i];
    }
    esq_c[tid] = g_esq[n*1024 + mc*128 + tid];
    __syncthreads();

    const int cnt = g_ucnt[n];
    const unsigned code_m = (unsigned)(mc*128 + tid);

    for (int g0 = slice*8; g0 < cnt; g0 += 16*8) {
        // load xs for rows g0..g0+7 (clamped; invalid rows guarded at atomic)
        #pragma unroll
        for (int r = 0; r < 8; r++) {
            int u = g0 + r;
            int uc = (u < cnt) ? u : (cnt - 1);
            int l = g_ulistn[n*LPER + uc];
            int b = l >> 6, h = l & 63;
            xs[r*128 + tid] = x[(size_t)b*65536 + (size_t)n*8192 + tid*64 + h];
        }
        if (tid < 8) {
            int u = g0 + tid;
            int uc = (u < cnt) ? u : (cnt - 1);
            xsq_s[tid] = g_xsq[n*LPER + g_ulistn[n*LPER + uc]];
        }
        __syncthreads();

        // 8 exact ascending-d chains, E read once per code per q
        float c[8];
        #pragma unroll
        for (int r = 0; r < 8; r++) c[r] = 0.f;
        const float4* er4 = (const float4*)&E[tid*132];
        #pragma unroll 8
        for (int qq = 0; qq < 32; qq++) {
            float4 e = er4[qq];
            #pragma unroll
            for (int r = 0; r < 8; r++) {
                float4 xr = *(const float4*)&xs[r*128 + qq*4];
                c[r] = fmaf(xr.x, e.x, c[r]);
                c[r] = fmaf(xr.y, e.y, c[r]);
                c[r] = fmaf(xr.z, e.z, c[r]);
                c[r] = fmaf(xr.w, e.w, c[r]);
            }
        }

        // per-row reduction to packed (dist,m) keys
        #pragma unroll
        for (int r = 0; r < 8; r++) {
            float D = __fsub_rn(__fadd_rn(esq_c[tid], xsq_s[r]), 2.f*c[r]);
            unsigned ud = __float_as_uint(D);
            ud = (ud & 0x80000000u) ? ~ud : (ud | 0x80000000u);
            unsigned long long key = ((unsigned long long)ud << 32) | code_m;
            #pragma unroll
            for (int o = 16; o; o >>= 1) {
                unsigned long long ok = __shfl_xor_sync(0xffffffffu, key, o);
                if (ok < key) key = ok;
            }
            if (lane == 0) wred[wid*8 + r] = key;
        }
        __syncthreads();
        if (tid < 8) {
            int u = g0 + tid;
            if (u < cnt) {
                unsigned long long k = wred[tid];
                if (wred[8  + tid] < k) k = wred[8  + tid];
                if (wred[16 + tid] < k) k = wred[16 + tid];
                if (wred[24 + tid] < k) k = wred[24 + tid];
                int l = g_ulistn[n*LPER + u];
                atomicMin(&g_fixkey[n*LPER + l], k);
            }
        }
        __syncthreads();
    }
}

// ---------------- unpack fixed indices (per-codebook lists) ----------------
__global__ void unpack_kernel() {
    const int n = blockIdx.x;
    const int cnt = g_ucnt[n];
    for (int p = threadIdx.x; p < cnt; p += blockDim.x) {
        int l = g_ulistn[n*LPER + p];
        int id = n*LPER + l;
        g_indices[id] = (int)(unsigned)(g_fixkey[id] & 0xFFFFFFFFull);
    }
}

// ---------------- gather + z_q + loss partials + indices out ----------------
__global__ void __launch_bounds__(256)
gather_kernel(const float* __restrict__ x, const float* __restrict__ emb,
              float* __restrict__ out, float* __restrict__ out_idx, int write_extras) {
    __shared__ int   midx[64];
    __shared__ float rows[64*129];
    __shared__ float red[256];
    const int n = blockIdx.x & 7, b = blockIdx.x >> 3, tid = threadIdx.x;

    if (tid < 64) {
        int m = g_indices[n*LPER + b*HLAT + tid];
        midx[tid] = m;
        if (write_extras) out_idx[b*(NCB*HLAT) + n*HLAT + tid] = (float)m;
    }
    __syncthreads();
    for (int idx = tid; idx < 64*128; idx += 256) {
        int r = idx >> 7, d = idx & 127;
        rows[r*129 + d] = emb[(size_t)n*(MEMB*DEMB) + (size_t)midx[r]*DEMB + d];
    }
    __syncthreads();
    float s = 0.f;
    const size_t base = (size_t)b*65536 + (size_t)n*8192;
    for (int idx = tid; idx < 8192; idx += 256) {
        int d = idx >> 6, h = idx & 63;
        float q  = rows[h*129 + d];
        float xv = x[base + idx];
        out[base + idx] = q;
        float df = xv - q;
        s += df*df;
    }
    red[tid] = s;
    __syncthreads();
    for (int st = 128; st; st >>= 1) { if (tid < st) red[tid] += red[tid+st]; __syncthreads(); }
    if (tid == 0) g_part[blockIdx.x] = red[0];
}

// ---------------- entropy ----------------
__global__ void entropy_kernel() {
    __shared__ int   hist[MEMB];
    __shared__ float red[256];
    const int n = blockIdx.x, tid = threadIdx.x;
    for (int i = tid; i < MEMB; i += 256) hist[i] = 0;
    __syncthreads();
    for (int l = tid; l < LPER; l += 256) atomicAdd(&hist[g_indices[n*LPER + l]], 1);
    __syncthreads();
    float s = 0.f;
    for (int m = tid; m < MEMB; m += 256) {
        float p = (float)hist[m] * (1.f / (float)LPER);
        s += p * logf(p + 1e-10f);
    }
    red[tid] = s;
    __syncthreads();
    for (int st = 128; st; st >>= 1) { if (tid < st) red[tid] += red[tid+st]; __syncthreads(); }
    if (tid == 0) g_ent[n] = -red[0];
}

// ---------------- finalize ----------------
__global__ void finalize_kernel(float* __restrict__ out, int write_scalars) {
    __shared__ float red[256];
    const int tid = threadIdx.x;
    float s = 0.f;
    for (int i = tid; i < 2048; i += 256) s += g_part[i];
    red[tid] = s;
    __syncthreads();
    for (int st = 128; st; st >>= 1) { if (tid < st) red[tid] += red[tid+st]; __syncthreads(); }
    if (tid == 0 && write_scalars) {
        float loss = 0.25f * red[0] / (float)ZQ_ELEMS;
        float ent = 0.f, perp = 0.f;
        #pragma unroll
        for (int n = 0; n < NCB; n++) { ent += g_ent[n]; perp += expf(g_ent[n]); }
        out[ZQ_ELEMS + 0] = loss;
        out[ZQ_ELEMS + 1] = ent * (1.f / NCB);
        out[ZQ_ELEMS + 2] = perp * (1.f / NCB);
    }
}

// ---------------- launch ----------------
extern "C" void kernel_launch(void* const* d_in, const int* in_sizes, int n_in,
                              void* d_out, int out_size) {
    const float* x   = (const float*)d_in[0];
    const float* emb = (const float*)d_in[1];
    if (n_in >= 2 && in_sizes[0] == NCB*MEMB*DEMB && in_sizes[1] == ZQ_ELEMS) {
        const float* t = x; x = emb; emb = t;
    }
    float* out = (float*)d_out;
    const int full = (out_size >= ZQ_ELEMS + 3 + IDX_ELEMS) ? 1 : 0;

    const int SMEM_ARG = 105472 + 1024;
    cudaFuncSetAttribute(argmin_mma, cudaFuncAttributeMaxDynamicSharedMemorySize, SMEM_ARG);
    const int SMEM_FIX = (128*132 + 8*128 + 128 + 8) * 4 + 32 * 8;   // 72480
    cudaFuncSetAttribute(fixup_kernel, cudaFuncAttributeMaxDynamicSharedMemorySize, SMEM_FIX);

    esq_kernel<<<(NCB*MEMB + 255)/256, 256>>>(emb);
    xsq_kernel<<<BATCH*NCB, 256>>>(x);
    bprep_kernel<<<(NCB*MEMB*DEMB + 255)/256, 256>>>(emb);
    argmin_mma<<<NCB * (LPER/64), 256, SMEM_ARG>>>(x);
    fixup_kernel<<<NCB*8*16, 128, SMEM_FIX>>>(x, emb);
    unpack_kernel<<<NCB, 256>>>();
    gather_kernel<<<BATCH*NCB, 256>>>(x, emb, out, out + ZQ_ELEMS + 3, full);
    entropy_kernel<<<NCB, 256>>>();
    finalize_kernel<<<1, 256>>>(out, full);
}

// round 11
// speedup vs baseline: 1.6926x; 1.0860x over previous
#include <cuda_runtime.h>
#include <cuda_fp16.h>
#include <math.h>
#include <stdint.h>

#define NCB   8
#define MEMB  1024
#define DEMB  128
#define HLAT  64
#define BATCH 256
#define LPER  (BATCH*HLAT)              /* 16384 per codebook */
#define ZQ_ELEMS (BATCH*NCB*DEMB*HLAT)  /* 16777216 */
#define IDX_ELEMS (BATCH*NCB*HLAT)      /* 131072 */

// ---------------- device scratch ----------------
__device__ int   g_indices[NCB*LPER];
__device__ float g_esq[NCB*MEMB];
__device__ int   g_esqmaxb[NCB];          // max esq per codebook (float bits, >0)
__device__ float g_xsq[NCB*LPER];
__device__ float g_part[2048];
__device__ float g_ent[NCB];
__device__ int   g_ucnt[NCB];             // per-codebook uncertain counts
__device__ int   g_ulistn[NCB*LPER];      // per-codebook lists of l values
__device__ unsigned long long g_fixkey[NCB*LPER];
__device__ float g_xpack[(size_t)NCB*LPER*DEMB]; // packed x rows per (n, list slot)
// pre-swizzled fp16 embedding tiles (e*256): [n][mchunk 16][row 64][k 128]
__device__ __half g_bh[NCB*MEMB*DEMB];

// ---------------- PTX helpers ----------------
__device__ __forceinline__ uint32_t smem_u32(const void* p) {
    uint32_t a;
    asm("{ .reg .u64 t; cvta.to.shared.u64 t, %1; cvt.u32.u64 %0, t; }" : "=r"(a) : "l"(p));
    return a;
}
__device__ __forceinline__ void ldsm4(uint32_t* r, uint32_t addr) {
    asm volatile("ldmatrix.sync.aligned.m8n8.x4.shared.b16 {%0,%1,%2,%3}, [%4];"
        : "=r"(r[0]), "=r"(r[1]), "=r"(r[2]), "=r"(r[3]) : "r"(addr));
}
__device__ __forceinline__ void mma_f16(float* c, const uint32_t* a, const uint32_t* b) {
    asm volatile("mma.sync.aligned.m16n8k16.row.col.f32.f16.f16.f32 "
        "{%0,%1,%2,%3}, {%4,%5,%6,%7}, {%8,%9}, {%0,%1,%2,%3};"
        : "+f"(c[0]), "+f"(c[1]), "+f"(c[2]), "+f"(c[3])
        : "r"(a[0]), "r"(a[1]), "r"(a[2]), "r"(a[3]), "r"(b[0]), "r"(b[1]));
}
__device__ __forceinline__ void cp16(uint32_t dst, const void* src) {
    asm volatile("cp.async.cg.shared.global [%0], [%1], 16;" :: "r"(dst), "l"(src) : "memory");
}
#define CP_COMMIT() asm volatile("cp.async.commit_group;" ::: "memory")
#define CP_WAIT(n)  asm volatile("cp.async.wait_group %0;" :: "n"(n) : "memory")

// ---------------- e_sq (exact sequential) + per-n max + count reset ----------------
__global__ void esq_kernel(const float* __restrict__ emb) {
    int t = blockIdx.x * blockDim.x + threadIdx.x;
    if (t < NCB) g_ucnt[t] = 0;
    if (t >= NCB*MEMB) return;
    const float* row = emb + (size_t)t * DEMB;
    float acc = 0.f;
    #pragma unroll 8
    for (int d = 0; d < DEMB; d++) {
        float v = row[d];
        acc = __fadd_rn(acc, __fmul_rn(v, v));
    }
    g_esq[t] = acc;
    atomicMax(&g_esqmaxb[t >> 10], __float_as_int(acc));   // acc > 0
}

// ---------------- x_sq (exact sequential) ----------------
__global__ void __launch_bounds__(256)
xsq_kernel(const float* __restrict__ x) {
    __shared__ float tile[8192];
    const int n = blockIdx.x & 7, b = blockIdx.x >> 3, tid = threadIdx.x;
    const size_t base = (size_t)b*65536 + (size_t)n*8192;
    for (int i = tid; i < 8192; i += 256) tile[i] = x[base + i];
    __syncthreads();
    if (tid < 64) {
        float acc = 0.f;
        #pragma unroll 8
        for (int d = 0; d < DEMB; d++) {
            float v = tile[d*64 + tid];
            acc = __fadd_rn(acc, __fmul_rn(v, v));
        }
        g_xsq[n*LPER + b*HLAT + tid] = acc;
    }
}

// ---------------- embedding -> swizzled fp16 (e*256) tiles, 64-code chunks ----------------
__global__ void bprep_kernel(const float* __restrict__ emb) {
    int u = blockIdx.x * blockDim.x + threadIdx.x;
    if (u >= NCB*MEMB*DEMB) return;
    float v = emb[u] * 256.0f;               // exact scale
    int d = u & 127, m = (u >> 7) & 1023, n = u >> 17;
    int row = m & 63, mc = m >> 6;
    int elem = ((n*16 + mc)*64 + row)*128 + (((d >> 3) ^ (row & 7)) << 3) + (d & 7);
    g_bh[elem] = __float2half_rn(v);
}

// ---------------- pass 1: fp16 2-MMA approximate argmin ----------------
// CTA = (n, batch row). 8 warps = 2(l) x 4(m); warp tile 32x16.
// m-chunks of 64 codes (16 iters), B double-buffered 2x16KB -> 3 CTAs/SM.
__global__ void __launch_bounds__(256, 3)
argmin_mma(const float* __restrict__ x) {
    extern __shared__ char smraw[];
    uint32_t sraw = smem_u32(smraw);
    uint32_t sb = (sraw + 1023u) & ~1023u;
    char* sm = smraw + (sb - sraw);
    __half* Ahi = (__half*)(sm);              // 16KB @0
    __half* Alo = (__half*)(sm + 16384);      // 16KB
    // B buffers: buf0 @32768 (16KB), buf1 @49152 (16KB)
    float* esq_s = (float*)(sm + 65536);      // 4KB
    float* sbest = (float*)(sm + 69632);      // 256 f32
    float* ssec  = (float*)(sm + 70656);      // 256 f32
    int*   sidx  = (int*)  (sm + 71680);      // 256 int

    const int n  = blockIdx.x >> 8;
    const int lt = blockIdx.x & 255;          // batch row b
    const int l0 = lt * 64;
    const int tid  = threadIdx.x;
    const int lane = tid & 31;
    const int w    = tid >> 5;
    const int wl   = w & 1;     // l half (32 rows)
    const int wm   = w >> 1;    // m quarter (16 cols of the 64-chunk)

    // ---- prefetch B chunk 0 into buf0 ----
    {
        const char* src = (const char*)(g_bh + ((size_t)(n*16 + 0) << 13));
        uint32_t dst = sb + 32768;
        #pragma unroll
        for (int i = 0; i < 4; i++)
            cp16(dst + (tid + i*256)*16, src + (tid + i*256)*16);
        CP_COMMIT();
    }

    // stage e_sq
    for (int i = tid; i < 1024; i += 256) esq_s[i] = g_esq[n*1024 + i];

    // stage + fp16-split A tile (swizzled): rows j = h (0..63), cols d
    for (int idx = tid; idx < 8192; idx += 256) {
        int d = idx >> 6, j = idx & 63;
        float v = x[(size_t)lt*65536 + (size_t)n*8192 + d*64 + j];
        __half h = __float2half_rn(v);
        __half l = __float2half_rn(v - __half2float(h));
        int elem = j*128 + (((d >> 3) ^ (j & 7)) << 3) + (d & 7);
        Ahi[elem] = h; Alo[elem] = l;
    }

    // ldmatrix per-lane address precompute
    const uint32_t sAh = sb, sBh0 = sb + 32768;
    const int q  = lane >> 3;
    const int r8 = lane & 7;
    const int cqA = q >> 1;
    const int cqB = q & 1;
    uint32_t aBase[2]; int a7[2];
    #pragma unroll
    for (int t2 = 0; t2 < 2; t2++) {
        int rowA = wl*32 + t2*16 + r8 + (q & 1)*8;
        aBase[t2] = sAh + rowA*256; a7[t2] = rowA & 7;
    }
    uint32_t bBase; int b7;
    {
        int rowB = wm*16 + r8 + (q >> 1)*8;
        bBase = sBh0 + rowB*256; b7 = rowB & 7;
    }

    float best[4], sec[4];
    int   idxm[4];
    #pragma unroll
    for (int s = 0; s < 4; s++) { best[s] = 3.4e38f; sec[s] = 3.4e38f; idxm[s] = 0; }

    const int col2 = (lane & 3) * 2;

    for (int mc = 0; mc < 16; mc++) {
        if (mc < 15) {
            const char* src = (const char*)(g_bh + ((size_t)(n*16 + mc + 1) << 13));
            uint32_t dbuf = sb + 32768 + (uint32_t)(((mc + 1) & 1) * 16384);
            #pragma unroll
            for (int i = 0; i < 4; i++)
                cp16(dbuf + (tid + i*256)*16, src + (tid + i*256)*16);
            CP_COMMIT();
            CP_WAIT(1);
        } else {
            CP_WAIT(0);
        }
        __syncthreads();   // current buffer visible (also covers A on mc=0)

        const uint32_t bufOff = (uint32_t)((mc & 1) * 16384);

        float acc[2][2][4];
        #pragma unroll
        for (int t2 = 0; t2 < 2; t2++)
            #pragma unroll
            for (int mt = 0; mt < 2; mt++)
                #pragma unroll
                for (int c = 0; c < 4; c++) acc[t2][mt][c] = 0.f;

        #pragma unroll
        for (int ks = 0; ks < 8; ks++) {
            const int ks2 = ks * 2;
            uint32_t ah[2][4], al[2][4];
            #pragma unroll
            for (int t2 = 0; t2 < 2; t2++) {
                uint32_t off = (uint32_t)(((ks2 + cqA) ^ a7[t2]) << 4);
                ldsm4(ah[t2], aBase[t2] + off);
                ldsm4(al[t2], aBase[t2] + off + 16384);
            }
            uint32_t bh[4];
            {
                uint32_t off = (uint32_t)(((ks2 + cqB) ^ b7) << 4) + bufOff;
                ldsm4(bh, bBase + off);
            }
            #pragma unroll
            for (int t2 = 0; t2 < 2; t2++) {
                mma_f16(acc[t2][0], ah[t2], &bh[0]);
                mma_f16(acc[t2][1], ah[t2], &bh[2]);
                mma_f16(acc[t2][0], al[t2], &bh[0]);
                mma_f16(acc[t2][1], al[t2], &bh[2]);
            }
        }

        // epilogue: t = esq - acc/128  (acc = 256*dot; 2*dot = acc*2^-7)
        const int mbase = mc*64 + wm*16;
        #pragma unroll
        for (int t2 = 0; t2 < 2; t2++) {
            #pragma unroll
            for (int mt = 0; mt < 2; mt++) {
                float e0 = esq_s[mbase + mt*8 + col2];
                float e1 = esq_s[mbase + mt*8 + col2 + 1];
                int m0 = mbase + mt*8 + col2;
                {
                    int s = t2*2;
                    float ta = fmaf(acc[t2][mt][0], -0.0078125f, e0);
                    float tb = fmaf(acc[t2][mt][1], -0.0078125f, e1);
                    if (ta < best[s]) { sec[s] = best[s]; best[s] = ta; idxm[s] = m0; }
                    else if (ta < sec[s]) sec[s] = ta;
                    if (tb < best[s]) { sec[s] = best[s]; best[s] = tb; idxm[s] = m0 + 1; }
                    else if (tb < sec[s]) sec[s] = tb;
                }
                {
                    int s = t2*2 + 1;
                    float ta = fmaf(acc[t2][mt][2], -0.0078125f, e0);
                    float tb = fmaf(acc[t2][mt][3], -0.0078125f, e1);
                    if (ta < best[s]) { sec[s] = best[s]; best[s] = ta; idxm[s] = m0; }
                    else if (ta < sec[s]) sec[s] = ta;
                    if (tb < best[s]) { sec[s] = best[s]; best[s] = tb; idxm[s] = m0 + 1; }
                    else if (tb < sec[s]) sec[s] = tb;
                }
            }
        }
        __syncthreads();   // all warps done reading this buffer before overwrite
    }

    // quad reduce (lanes sharing lane>>2 hold the same rows)
    #pragma unroll
    for (int s = 0; s < 4; s++) {
        float b = best[s], sc = sec[s];
        int   im = idxm[s];
        #pragma unroll
        for (int off = 1; off <= 2; off <<= 1) {
            float ob = __shfl_xor_sync(0xffffffffu, b,  off);
            float os = __shfl_xor_sync(0xffffffffu, sc, off);
            int   oi = __shfl_xor_sync(0xffffffffu, im, off);
            if (ob < b || (ob == b && oi < im)) {
                sc = fminf(b, os); b = ob; im = oi;
            } else {
                sc = fminf(sc, ob);
            }
        }
        best[s] = b; sec[s] = sc; idxm[s] = im;
    }
    if ((lane & 3) == 0) {
        const int g = lane >> 2;
        #pragma unroll
        for (int s = 0; s < 4; s++) {
            int row = wl*32 + (s >> 1)*16 + g + (s & 1)*8;
            sbest[wm*64 + row] = best[s];
            ssec [wm*64 + row] = sec[s];
            sidx [wm*64 + row] = idxm[s];
        }
    }
    __syncthreads();

    if (tid < 64) {
        float b = sbest[tid], s = ssec[tid];
        int   im = sidx[tid];
        #pragma unroll
        for (int qq = 1; qq < 4; qq++) {
            float bq = sbest[qq*64 + tid];
            float sq = ssec [qq*64 + tid];
            int   iq = sidx [qq*64 + tid];
            if (bq < b || (bq == b && iq < im)) { s = fminf(b, sq); b = bq; im = iq; }
            else { s = fminf(s, bq); }
        }
        int l = l0 + tid;
        int id = n*LPER + l;
        g_indices[id] = im;
        // rigorous per-row margin: 2^-9*sqrt(xsq*esqmax) + slack
        float mar = 0.001953125f * sqrtf(g_xsq[id] * __int_as_float(g_esqmaxb[n])) + 1.2e-4f;
        if (s - b < mar) {
            g_fixkey[id] = 0xFFFFFFFFFFFFFFFFull;
            int p = atomicAdd(&g_ucnt[n], 1);
            g_ulistn[n*LPER + p] = l;
        }
    }
}

// ---------------- pack flagged x rows (one gather per row, coalesced writes) ----------------
__global__ void __launch_bounds__(128)
pack_kernel(const float* __restrict__ x) {
    const int n = blockIdx.y;
    const int cnt = g_ucnt[n];
    for (int p = blockIdx.x; p < cnt; p += gridDim.x) {
        int l = g_ulistn[n*LPER + p];
        int b = l >> 6, h = l & 63;
        g_xpack[((size_t)n*LPER + p)*128 + threadIdx.x] =
            x[(size_t)b*65536 + (size_t)n*8192 + threadIdx.x*64 + h];
    }
}

// ---------------- pass 2: batched exact rescan (packed xs, 8-row batches) ----------------
__global__ void __launch_bounds__(128)
fixup_kernel(const float* __restrict__ emb) {
    extern __shared__ float fsm[];
    float* E     = fsm;                       // [128 codes][stride 132]
    float* xs    = fsm + 128*132;             // [8 rows][128]
    float* esq_c = xs + 1024;                 // [128]
    float* xsq_s = esq_c + 128;               // [8]
    unsigned long long* wred = (unsigned long long*)(xsq_s + 8);   // [4 warps][8 rows]

    const int n     = blockIdx.x >> 7;
    const int mc    = (blockIdx.x >> 4) & 7;
    const int slice = blockIdx.x & 15;
    const int tid   = threadIdx.x;            // code within chunk
    const int wid   = tid >> 5, lane = tid & 31;

    // stage E chunk (coalesced reads; stride-132 rows -> conflict-free LDS.128)
    const float* src = emb + ((size_t)n*1024 + mc*128)*128;
    for (int i = tid; i < 16384; i += 128) {
        int r = i >> 7, d = i & 127;
        E[r*132 + d] = src[i];
    }
    esq_c[tid] = g_esq[n*1024 + mc*128 + tid];
    __syncthreads();

    const int cnt = g_ucnt[n];
    const unsigned code_m = (unsigned)(mc*128 + tid);

    for (int g0 = slice*8; g0 < cnt; g0 += 16*8) {
        // coalesced xs loads from packed buffer
        #pragma unroll
        for (int r = 0; r < 8; r++) {
            int u = g0 + r;
            int uc = (u < cnt) ? u : (cnt - 1);
            xs[r*128 + tid] = g_xpack[((size_t)n*LPER + uc)*128 + tid];
        }
        if (tid < 8) {
            int u = g0 + tid;
            int uc = (u < cnt) ? u : (cnt - 1);
            xsq_s[tid] = g_xsq[n*LPER + g_ulistn[n*LPER + uc]];
        }
        __syncthreads();

        // 8 exact ascending-d chains, E read once per code per q
        float c[8];
        #pragma unroll
        for (int r = 0; r < 8; r++) c[r] = 0.f;
        const float4* er4 = (const float4*)&E[tid*132];
        #pragma unroll 8
        for (int qq = 0; qq < 32; qq++) {
            float4 e = er4[qq];
            #pragma unroll
            for (int r = 0; r < 8; r++) {
                float4 xr = *(const float4*)&xs[r*128 + qq*4];
                c[r] = fmaf(xr.x, e.x, c[r]);
                c[r] = fmaf(xr.y, e.y, c[r]);
                c[r] = fmaf(xr.z, e.z, c[r]);
                c[r] = fmaf(xr.w, e.w, c[r]);
            }
        }

        // per-row reduction to packed (dist,m) keys
        #pragma unroll
        for (int r = 0; r < 8; r++) {
            float D = __fsub_rn(__fadd_rn(esq_c[tid], xsq_s[r]), 2.f*c[r]);
            unsigned ud = __float_as_uint(D);
            ud = (ud & 0x80000000u) ? ~ud : (ud | 0x80000000u);
            unsigned long long key = ((unsigned long long)ud << 32) | code_m;
            #pragma unroll
            for (int o = 16; o; o >>= 1) {
                unsigned long long ok = __shfl_xor_sync(0xffffffffu, key, o);
                if (ok < key) key = ok;
            }
            if (lane == 0) wred[wid*8 + r] = key;
        }
        __syncthreads();
        if (tid < 8) {
            int u = g0 + tid;
            if (u < cnt) {
                unsigned long long k = wred[tid];
                if (wred[8  + tid] < k) k = wred[8  + tid];
                if (wred[16 + tid] < k) k = wred[16 + tid];
                if (wred[24 + tid] < k) k = wred[24 + tid];
                int l = g_ulistn[n*LPER + u];
                atomicMin(&g_fixkey[n*LPER + l], k);
            }
        }
        __syncthreads();
    }
}

// ---------------- unpack fixed indices (per-codebook lists) ----------------
__global__ void unpack_kernel() {
    const int n = blockIdx.x;
    const int cnt = g_ucnt[n];
    for (int p = threadIdx.x; p < cnt; p += blockDim.x) {
        int l = g_ulistn[n*LPER + p];
        int id = n*LPER + l;
        g_indices[id] = (int)(unsigned)(g_fixkey[id] & 0xFFFFFFFFull);
    }
}

// ---------------- gather + z_q + loss partials + indices out (float4) ----------------
__global__ void __launch_bounds__(256)
gather_kernel(const float* __restrict__ x, const float* __restrict__ emb,
              float* __restrict__ out, float* __restrict__ out_idx, int write_extras) {
    __shared__ int   midx[64];
    __shared__ float rows[64*129];
    __shared__ float red[256];
    const int n = blockIdx.x & 7, b = blockIdx.x >> 3, tid = threadIdx.x;

    if (tid < 64) {
        int m = g_indices[n*LPER + b*HLAT + tid];
        midx[tid] = m;
        if (write_extras) out_idx[b*(NCB*HLAT) + n*HLAT + tid] = (float)m;
    }
    __syncthreads();
    for (int idx = tid; idx < 64*32; idx += 256) {    // float4 staging of 64 emb rows
        int r = idx >> 5, dq = (idx & 31) * 4;
        float4 v = *(const float4*)&emb[((size_t)n*MEMB + midx[r])*DEMB + dq];
        float* dst = &rows[r*129 + dq];
        dst[0] = v.x; dst[1] = v.y; dst[2] = v.z; dst[3] = v.w;
    }
    __syncthreads();
    float s = 0.f;
    const size_t base = (size_t)b*65536 + (size_t)n*8192;
    for (int idx4 = tid; idx4 < 2048; idx4 += 256) {  // idx4 -> (d, h4): out idx = d*64 + h4*4
        int d = idx4 >> 4, h4 = (idx4 & 15) * 4;
        float4 q;
        q.x = rows[(h4+0)*129 + d];
        q.y = rows[(h4+1)*129 + d];
        q.z = rows[(h4+2)*129 + d];
        q.w = rows[(h4+3)*129 + d];
        float4 xv = *(const float4*)&x[base + d*64 + h4];
        *(float4*)&out[base + d*64 + h4] = q;
        float dx = xv.x - q.x, dy = xv.y - q.y, dz = xv.z - q.z, dw = xv.w - q.w;
        s += dx*dx + dy*dy + dz*dz + dw*dw;
    }
    red[tid] = s;
    __syncthreads();
    for (int st = 128; st; st >>= 1) { if (tid < st) red[tid] += red[tid+st]; __syncthreads(); }
    if (tid == 0) g_part[blockIdx.x] = red[0];
}

// ---------------- entropy ----------------
__global__ void entropy_kernel() {
    __shared__ int   hist[MEMB];
    __shared__ float red[256];
    const int n = blockIdx.x, tid = threadIdx.x;
    for (int i = tid; i < MEMB; i += 256) hist[i] = 0;
    __syncthreads();
    for (int l = tid; l < LPER; l += 256) atomicAdd(&hist[g_indices[n*LPER + l]], 1);
    __syncthreads();
    float s = 0.f;
    for (int m = tid; m < MEMB; m += 256) {
        float p = (float)hist[m] * (1.f / (float)LPER);
        s += p * logf(p + 1e-10f);
    }
    red[tid] = s;
    __syncthreads();
    for (int st = 128; st; st >>= 1) { if (tid < st) red[tid] += red[tid+st]; __syncthreads(); }
    if (tid == 0) g_ent[n] = -red[0];
}

// ---------------- finalize ----------------
__global__ void finalize_kernel(float* __restrict__ out, int write_scalars) {
    __shared__ float red[256];
    const int tid = threadIdx.x;
    float s = 0.f;
    for (int i = tid; i < 2048; i += 256) s += g_part[i];
    red[tid] = s;
    __syncthreads();
    for (int st = 128; st; st >>= 1) { if (tid < st) red[tid] += red[tid+st]; __syncthreads(); }
    if (tid == 0 && write_scalars) {
        float loss = 0.25f * red[0] / (float)ZQ_ELEMS;
        float ent = 0.f, perp = 0.f;
        #pragma unroll
        for (int n = 0; n < NCB; n++) { ent += g_ent[n]; perp += expf(g_ent[n]); }
        out[ZQ_ELEMS + 0] = loss;
        out[ZQ_ELEMS + 1] = ent * (1.f / NCB);
        out[ZQ_ELEMS + 2] = perp * (1.f / NCB);
    }
}

// ---------------- launch ----------------
extern "C" void kernel_launch(void* const* d_in, const int* in_sizes, int n_in,
                              void* d_out, int out_size) {
    const float* x   = (const float*)d_in[0];
    const float* emb = (const float*)d_in[1];
    if (n_in >= 2 && in_sizes[0] == NCB*MEMB*DEMB && in_sizes[1] == ZQ_ELEMS) {
        const float* t = x; x = emb; emb = t;
    }
    float* out = (float*)d_out;
    const int full = (out_size >= ZQ_ELEMS + 3 + IDX_ELEMS) ? 1 : 0;

    const int SMEM_ARG = 72704 + 1024;
    cudaFuncSetAttribute(argmin_mma, cudaFuncAttributeMaxDynamicSharedMemorySize, SMEM_ARG);
    const int SMEM_FIX = (128*132 + 8*128 + 128 + 8) * 4 + 32 * 8;   // 72480
    cudaFuncSetAttribute(fixup_kernel, cudaFuncAttributeMaxDynamicSharedMemorySize, SMEM_FIX);

    esq_kernel<<<(NCB*MEMB + 255)/256, 256>>>(emb);
    xsq_kernel<<<BATCH*NCB, 256>>>(x);
    bprep_kernel<<<(NCB*MEMB*DEMB + 255)/256, 256>>>(emb);
    argmin_mma<<<NCB * (LPER/64), 256, SMEM_ARG>>>(x);
    pack_kernel<<<dim3(256, NCB), 128>>>(x);
    fixup_kernel<<<NCB*8*16, 128, SMEM_FIX>>>(emb);
    unpack_kernel<<<NCB, 256>>>();
    gather_kernel<<<BATCH*NCB, 256>>>(x, emb, out, out + ZQ_ELEMS + 3, full);
    entropy_kernel<<<NCB, 256>>>();
    finalize_kernel<<<1, 256>>>(out, full);
}